// round 2
// baseline (speedup 1.0000x reference)
#include <cuda_runtime.h>

// Problem constants (fixed shapes for this problem)
#define N_NODES 20000
#define F_IN    8
#define T_P     12
#define HID     32
#define FEAT    96      // F_IN * T_P floats per node
#define E_MAX   320000

// ---------------- device scratch (no allocations allowed) ----------------
__device__ int   g_cnt [N_NODES];        // in-degree (edges only)
__device__ int   g_off [N_NODES];        // CSR offsets (exclusive scan of cnt)
__device__ int   g_cur [N_NODES];        // fill cursors
__device__ int   g_csrc[E_MAX];          // edge sources, grouped by dst
__device__ float g_dinv[N_NODES];        // 1/sqrt(deg+1)
__device__ float g_WLz [F_IN * HID];     // Wz @ Lz_top  (8 x 32)
__device__ float g_WLh [F_IN * HID];     // Wh @ Lh_top  (8 x 32)
__device__ float g_blz [HID];            // bz @ Lz_top + lz
__device__ float g_blh [HID];            // bh @ Lh_top + lh
__device__ float g_probs[T_P];           // softmax(att)

__device__ __forceinline__ float fast_tanh(float x) {
    float y;
    asm("tanh.approx.f32 %0, %1;" : "=f"(y) : "f"(x));
    return y;
}

// ---------------- kernels ----------------

// Zero histogram everywhere; block 0 additionally folds the gate weights
// (WL = W @ L_top, bl = b @ L_top + l) and computes softmax(att).
__global__ void k_zero_pre(const float* __restrict__ Wz, const float* __restrict__ bz,
                           const float* __restrict__ Wh, const float* __restrict__ bh,
                           const float* __restrict__ Lz, const float* __restrict__ lz,
                           const float* __restrict__ Lh, const float* __restrict__ lh,
                           const float* __restrict__ att) {
    int i = blockIdx.x * blockDim.x + threadIdx.x;
    if (i < N_NODES) g_cnt[i] = 0;

    if (blockIdx.x == 0) {
        int tid = threadIdx.x;
        if (tid < F_IN * HID) {
            int f = tid >> 5, h = tid & 31;
            float az = 0.f, ah = 0.f;
            #pragma unroll 8
            for (int k = 0; k < HID; k++) {
                az = fmaf(Wz[f * HID + k], Lz[k * HID + h], az);
                ah = fmaf(Wh[f * HID + k], Lh[k * HID + h], ah);
            }
            g_WLz[tid] = az;
            g_WLh[tid] = ah;
        }
        if (tid < HID) {
            float az = lz[tid], ah = lh[tid];
            for (int k = 0; k < HID; k++) {
                az = fmaf(bz[k], Lz[k * HID + tid], az);
                ah = fmaf(bh[k], Lh[k * HID + tid], ah);
            }
            g_blz[tid] = az;
            g_blh[tid] = ah;
        }
        if (tid == 0) {
            float m = -1e30f;
            for (int t = 0; t < T_P; t++) m = fmaxf(m, att[t]);
            float e[T_P], s = 0.f;
            for (int t = 0; t < T_P; t++) { e[t] = __expf(att[t] - m); s += e[t]; }
            float inv = 1.0f / s;
            for (int t = 0; t < T_P; t++) g_probs[t] = e[t] * inv;
        }
    }
}

__global__ void k_count(const int* __restrict__ dst, int E) {
    int i = blockIdx.x * blockDim.x + threadIdx.x;
    if (i < E) atomicAdd(&g_cnt[dst[i]], 1);
}

// Single-block exclusive scan of g_cnt -> g_off/g_cur, plus dinv = rsqrt(cnt+1).
#define SCAN_T 512
__global__ void k_scan() {
    __shared__ int part[SCAN_T];
    int tid = threadIdx.x;
    const int CH = (N_NODES + SCAN_T - 1) / SCAN_T;   // 40
    int base = tid * CH;
    int hi   = min(base + CH, N_NODES);

    int sum = 0;
    for (int i = base; i < hi; i++) sum += g_cnt[i];
    part[tid] = sum;
    __syncthreads();

    // Hillis–Steele inclusive scan of partials
    #pragma unroll
    for (int s = 1; s < SCAN_T; s <<= 1) {
        int v = (tid >= s) ? part[tid - s] : 0;
        __syncthreads();
        part[tid] += v;
        __syncthreads();
    }
    int run = part[tid] - sum;                        // exclusive prefix

    for (int i = base; i < hi; i++) {
        int c = g_cnt[i];
        g_off[i] = run;
        g_cur[i] = run;
        g_dinv[i] = rsqrtf((float)c + 1.0f);
        run += c;
    }
}

__global__ void k_fill(const int* __restrict__ src,
                       const int* __restrict__ dst, int E) {
    int i = blockIdx.x * blockDim.x + threadIdx.x;
    if (i < E) {
        int slot = atomicAdd(&g_cur[dst[i]], 1);
        g_csrc[slot] = src[i];
    }
}

// One warp per node: CSR gather + gates + attention + output projection, fused.
// agg[d] = dinv_d * (sum_s dinv_s * x_s) + dinv_d^2 * x_d
__global__ void k_gather(const float* __restrict__ x,
                         const float* __restrict__ Wout,
                         const float* __restrict__ bout,
                         float* __restrict__ out) {
    __shared__ float sh[8][FEAT];
    int w    = threadIdx.x >> 5;
    int lane = threadIdx.x & 31;
    int node = blockIdx.x * 8 + w;
    if (node >= N_NODES) return;

    int off = g_off[node];
    int cnt = g_cnt[node];

    float a0 = 0.f, a1 = 0.f, a2 = 0.f;
    for (int i = 0; i < cnt; i++) {
        int   s  = __ldg(&g_csrc[off + i]);
        float ds = __ldg(&g_dinv[s]);
        const float* xs = x + s * FEAT;
        a0 = fmaf(ds, __ldg(xs + lane),      a0);
        a1 = fmaf(ds, __ldg(xs + lane + 32), a1);
        a2 = fmaf(ds, __ldg(xs + lane + 64), a2);
    }
    float dn = g_dinv[node];
    float dn2 = dn * dn;
    const float* xn = x + node * FEAT;
    a0 = dn * a0 + dn2 * __ldg(xn + lane);
    a1 = dn * a1 + dn2 * __ldg(xn + lane + 32);
    a2 = dn * a2 + dn2 * __ldg(xn + lane + 64);

    sh[w][lane]      = a0;
    sh[w][lane + 32] = a1;
    sh[w][lane + 64] = a2;
    __syncwarp();

    // lane == hidden index h
    float wz[F_IN], wh[F_IN];
    #pragma unroll
    for (int f = 0; f < F_IN; f++) {
        wz[f] = g_WLz[f * HID + lane];
        wh[f] = g_WLh[f * HID + lane];
    }
    float bz0 = g_blz[lane];
    float bh0 = g_blh[lane];

    float hacc = 0.f;
    #pragma unroll
    for (int t = 0; t < T_P; t++) {
        float uz = bz0, uh = bh0;
        #pragma unroll
        for (int f = 0; f < F_IN; f++) {
            float xa = sh[w][f * T_P + t];       // broadcast read
            uz = fmaf(xa, wz[f], uz);
            uh = fmaf(xa, wh[f], uh);
        }
        // (1 - sigmoid(uz)) = 0.5*(1 - tanh(uz/2))
        float omz = 0.5f - 0.5f * fast_tanh(0.5f * uz);
        float ht  = fast_tanh(uh);
        hacc = fmaf(g_probs[t], omz * ht, hacc);
    }

    __syncwarp();
    sh[w][lane] = fmaxf(hacc, 0.f);              // relu(H_accum)
    __syncwarp();

    if (lane < T_P) {
        float acc = bout[lane];
        #pragma unroll
        for (int h = 0; h < HID; h++)
            acc = fmaf(sh[w][h], Wout[h * T_P + lane], acc);
        out[node * T_P + lane] = acc;
    }
}

// ---------------- launch ----------------
extern "C" void kernel_launch(void* const* d_in, const int* in_sizes, int n_in,
                              void* d_out, int out_size) {
    const float* x    = (const float*)d_in[0];   // (N, F_IN, T)
    const int*   ei   = (const int*)  d_in[1];   // (2, E)
    const float* Wz   = (const float*)d_in[2];
    const float* bz   = (const float*)d_in[3];
    // d_in[4], d_in[5]: Wr, br  (dead: H0 == 0)
    const float* Wh   = (const float*)d_in[6];
    const float* bh   = (const float*)d_in[7];
    const float* Lz   = (const float*)d_in[8];
    const float* lz   = (const float*)d_in[9];
    // d_in[10], d_in[11]: Lr, lr (dead)
    const float* Lh   = (const float*)d_in[12];
    const float* lh   = (const float*)d_in[13];
    const float* att  = (const float*)d_in[14];
    const float* Wout = (const float*)d_in[15];
    const float* bout = (const float*)d_in[16];
    float* out = (float*)d_out;

    int E = in_sizes[1] / 2;
    const int* src = ei;
    const int* dst = ei + E;

    k_zero_pre<<<(N_NODES + 255) / 256, 256>>>(Wz, bz, Wh, bh, Lz, lz, Lh, lh, att);
    k_count   <<<(E + 255) / 256, 256>>>(dst, E);
    k_scan    <<<1, SCAN_T>>>();
    k_fill    <<<(E + 255) / 256, 256>>>(src, dst, E);
    k_gather  <<<(N_NODES + 7) / 8, 256>>>(x, Wout, bout, out);
}

// round 3
// speedup vs baseline: 1.6563x; 1.6563x over previous
#include <cuda_runtime.h>

// Problem constants (fixed shapes for this problem)
#define N_NODES 20000
#define F_IN    8
#define T_P     12
#define HID     32
#define FEAT    96      // F_IN * T_P floats per node
#define FEAT4   24      // FEAT / 4

// ---------------- device scratch (no allocations allowed) ----------------
__device__ float  g_deg [N_NODES];               // degree + 1 (self loop)
__device__ float4 g_agg [N_NODES * FEAT4];       // sum over edges of dinv_s * x_s
__device__ float  g_WLz [F_IN * HID];            // Wz @ Lz_top  (8 x 32)
__device__ float  g_WLh [F_IN * HID];            // Wh @ Lh_top  (8 x 32)
__device__ float  g_blz [HID];                   // bz @ Lz_top + lz
__device__ float  g_blh [HID];                   // bh @ Lh_top + lh
__device__ float  g_probs[T_P];                  // softmax(att)

__device__ __forceinline__ float fast_tanh(float x) {
    float y;
    asm("tanh.approx.f32 %0, %1;" : "=f"(y) : "f"(x));
    return y;
}

// ---------------- kernels ----------------

// Fused init: zero agg, deg := 1, and (block 0) fold gate weights + softmax(att).
__global__ void k_init(const float* __restrict__ Wz, const float* __restrict__ bz,
                       const float* __restrict__ Wh, const float* __restrict__ bh,
                       const float* __restrict__ Lz, const float* __restrict__ lz,
                       const float* __restrict__ Lh, const float* __restrict__ lh,
                       const float* __restrict__ att) {
    int i = blockIdx.x * blockDim.x + threadIdx.x;
    if (i < N_NODES * FEAT4) g_agg[i] = make_float4(0.f, 0.f, 0.f, 0.f);
    if (i < N_NODES) g_deg[i] = 1.0f;            // +1 self-loop

    if (blockIdx.x == 0) {
        int tid = threadIdx.x;
        if (tid < F_IN * HID) {
            int f = tid >> 5, h = tid & 31;
            float az = 0.f, ah = 0.f;
            #pragma unroll 8
            for (int k = 0; k < HID; k++) {
                az = fmaf(Wz[f * HID + k], Lz[k * HID + h], az);
                ah = fmaf(Wh[f * HID + k], Lh[k * HID + h], ah);
            }
            g_WLz[tid] = az;
            g_WLh[tid] = ah;
        }
        if (tid < HID) {
            float az = lz[tid], ah = lh[tid];
            for (int k = 0; k < HID; k++) {
                az = fmaf(bz[k], Lz[k * HID + tid], az);
                ah = fmaf(bh[k], Lh[k * HID + tid], ah);
            }
            g_blz[tid] = az;
            g_blh[tid] = ah;
        }
        if (tid == 0) {
            float m = -1e30f;
            for (int t = 0; t < T_P; t++) m = fmaxf(m, att[t]);
            float e[T_P], s = 0.f;
            for (int t = 0; t < T_P; t++) { e[t] = __expf(att[t] - m); s += e[t]; }
            float inv = 1.0f / s;
            for (int t = 0; t < T_P; t++) g_probs[t] = e[t] * inv;
        }
    }
}

__global__ void k_count(const int* __restrict__ dst, int E) {
    int i = blockIdx.x * blockDim.x + threadIdx.x;
    if (i < E) atomicAdd(&g_deg[dst[i]], 1.0f);
}

// Scatter: agg[dst] += rsqrt(deg[src]) * x[src].   8 threads per edge,
// each thread handles 3 float4 chunks (lane-contiguous -> 128B coalesced).
__global__ void k_scatter(const float4* __restrict__ x4,
                          const int* __restrict__ src,
                          const int* __restrict__ dst, int E) {
    int i = blockIdx.x * blockDim.x + threadIdx.x;
    int e = i >> 3;
    if (e >= E) return;
    int sub = i & 7;
    int s = __ldg(&src[e]);
    int d = __ldg(&dst[e]);
    float ds = rsqrtf(__ldg(&g_deg[s]));

    const float4* xs = x4 + s * FEAT4;
    float4* ad = g_agg + d * FEAT4;
    #pragma unroll
    for (int k = 0; k < 3; k++) {
        int c = sub + k * 8;
        float4 v = __ldg(&xs[c]);
        asm volatile("red.global.add.v4.f32 [%0], {%1, %2, %3, %4};"
                     :: "l"(&ad[c]), "f"(v.x * ds), "f"(v.y * ds),
                        "f"(v.z * ds), "f"(v.w * ds)
                     : "memory");
    }
}

// One warp per node: finish normalization + self loop, gates, attention, output.
// agg_full[d] = dinv_d * g_agg[d] + (1/deg_d) * x[d]
__global__ void k_node(const float* __restrict__ x,
                       const float* __restrict__ Wout,
                       const float* __restrict__ bout,
                       float* __restrict__ out) {
    __shared__ float sh[8][FEAT];
    int w    = threadIdx.x >> 5;
    int lane = threadIdx.x & 31;
    int node = blockIdx.x * 8 + w;
    if (node >= N_NODES) return;

    float deg = g_deg[node];
    float dn  = rsqrtf(deg);
    float dn2 = 1.0f / deg;

    const float* agg = (const float*)g_agg + node * FEAT;
    const float* xn  = x + node * FEAT;
    sh[w][lane]      = dn * agg[lane]      + dn2 * __ldg(xn + lane);
    sh[w][lane + 32] = dn * agg[lane + 32] + dn2 * __ldg(xn + lane + 32);
    sh[w][lane + 64] = dn * agg[lane + 64] + dn2 * __ldg(xn + lane + 64);
    __syncwarp();

    // lane == hidden index h
    float wz[F_IN], wh[F_IN];
    #pragma unroll
    for (int f = 0; f < F_IN; f++) {
        wz[f] = g_WLz[f * HID + lane];
        wh[f] = g_WLh[f * HID + lane];
    }
    float bz0 = g_blz[lane];
    float bh0 = g_blh[lane];

    float hacc = 0.f;
    #pragma unroll
    for (int t = 0; t < T_P; t++) {
        float uz = bz0, uh = bh0;
        #pragma unroll
        for (int f = 0; f < F_IN; f++) {
            float xa = sh[w][f * T_P + t];       // broadcast read
            uz = fmaf(xa, wz[f], uz);
            uh = fmaf(xa, wh[f], uh);
        }
        // (1 - sigmoid(uz)) = 0.5*(1 - tanh(uz/2))
        float omz = 0.5f - 0.5f * fast_tanh(0.5f * uz);
        float ht  = fast_tanh(uh);
        hacc = fmaf(g_probs[t], omz * ht, hacc);
    }

    __syncwarp();
    sh[w][lane] = fmaxf(hacc, 0.f);              // relu(H_accum)
    __syncwarp();

    if (lane < T_P) {
        float acc = bout[lane];
        #pragma unroll
        for (int h = 0; h < HID; h++)
            acc = fmaf(sh[w][h], Wout[h * T_P + lane], acc);
        out[node * T_P + lane] = acc;
    }
}

// ---------------- launch ----------------
extern "C" void kernel_launch(void* const* d_in, const int* in_sizes, int n_in,
                              void* d_out, int out_size) {
    const float* x    = (const float*)d_in[0];   // (N, F_IN, T)
    const int*   ei   = (const int*)  d_in[1];   // (2, E)
    const float* Wz   = (const float*)d_in[2];
    const float* bz   = (const float*)d_in[3];
    // d_in[4], d_in[5]: Wr, br  (dead: H0 == 0)
    const float* Wh   = (const float*)d_in[6];
    const float* bh   = (const float*)d_in[7];
    const float* Lz   = (const float*)d_in[8];
    const float* lz   = (const float*)d_in[9];
    // d_in[10], d_in[11]: Lr, lr (dead)
    const float* Lh   = (const float*)d_in[12];
    const float* lh   = (const float*)d_in[13];
    const float* att  = (const float*)d_in[14];
    const float* Wout = (const float*)d_in[15];
    const float* bout = (const float*)d_in[16];
    float* out = (float*)d_out;

    int E = in_sizes[1] / 2;
    const int* src = ei;
    const int* dst = ei + E;

    const float4* x4 = (const float4*)x;

    k_init   <<<(N_NODES * FEAT4 + 255) / 256, 256>>>(Wz, bz, Wh, bh, Lz, lz, Lh, lh, att);
    k_count  <<<(E + 255) / 256, 256>>>(dst, E);
    k_scatter<<<(E * 8 + 255) / 256, 256>>>(x4, src, dst, E);
    k_node   <<<(N_NODES + 7) / 8, 256>>>(x, Wout, bout, out);
}